// round 1
// baseline (speedup 1.0000x reference)
#include <cuda_runtime.h>
#include <math.h>

// ---------------- problem constants ----------------
#define BSZ    2
#define LSEQ   4096
#define DMODEL 1024
#define DINNER 2048
#define DSTATE 16
#define DCONV  4
#define DTRANK 64
#define NTOK   (BSZ * LSEQ)                 // 8192
#define XPROJ  (DTRANK + 2 * DSTATE)        // 96

// ---------------- scratch (static device globals; no allocs) ----------------
__device__ float g_xz   [NTOK * 2 * DINNER];   // [8192, 4096]  u | z
__device__ float g_uact [NTOK * DINNER];       // [8192, 2048]
__device__ float g_xdbl [NTOK * XPROJ];        // [8192, 96]
__device__ float g_delta[NTOK * DINNER];       // [8192, 2048]
__device__ float g_y    [NTOK * DINNER];       // [8192, 2048]

// ---------------- generic NT SGEMM:  C[M,N] = A[M,K] * B[N,K]^T ----------------
// MODE 0: plain store.  MODE 1: C = softplus(acc + bias[n])
template <int BM, int BN, int BK, int TM, int TN, int MODE>
__global__ __launch_bounds__((BM / TM) * (BN / TN))
void sgemm_nt(int M, int N, int K,
              const float* __restrict__ A, int lda,
              const float* __restrict__ B, int ldb,
              float* __restrict__ C, int ldc,
              const float* __restrict__ bias)
{
    constexpr int THREADS = (BM / TM) * (BN / TN);
    __shared__ float As[BK][BM];
    __shared__ float Bs[BK][BN];

    const int brow = blockIdx.y * BM;
    const int bcol = blockIdx.x * BN;
    const int tid  = threadIdx.x;
    const int tcol = tid % (BN / TN);
    const int trow = tid / (BN / TN);

    float acc[TM][TN];
#pragma unroll
    for (int i = 0; i < TM; i++)
#pragma unroll
        for (int j = 0; j < TN; j++) acc[i][j] = 0.f;

    for (int k0 = 0; k0 < K; k0 += BK) {
        // load A tile (BM x BK), K-contiguous in global
#pragma unroll
        for (int i = tid; i < BM * BK; i += THREADS) {
            int m = i / BK, k = i % BK;
            As[k][m] = A[(long)(brow + m) * lda + k0 + k];
        }
        // load B tile (BN x BK)
#pragma unroll
        for (int i = tid; i < BN * BK; i += THREADS) {
            int n = i / BK, k = i % BK;
            Bs[k][n] = B[(long)(bcol + n) * ldb + k0 + k];
        }
        __syncthreads();

#pragma unroll
        for (int k = 0; k < BK; k++) {
            float ra[TM], rb[TN];
            if constexpr ((TM % 4) == 0) {
                const float4* a4 = reinterpret_cast<const float4*>(&As[k][trow * TM]);
#pragma unroll
                for (int i = 0; i < TM / 4; i++) {
                    float4 v = a4[i];
                    ra[4 * i + 0] = v.x; ra[4 * i + 1] = v.y;
                    ra[4 * i + 2] = v.z; ra[4 * i + 3] = v.w;
                }
            } else {
#pragma unroll
                for (int i = 0; i < TM; i++) ra[i] = As[k][trow * TM + i];
            }
            if constexpr ((TN % 4) == 0) {
                const float4* b4 = reinterpret_cast<const float4*>(&Bs[k][tcol * TN]);
#pragma unroll
                for (int j = 0; j < TN / 4; j++) {
                    float4 v = b4[j];
                    rb[4 * j + 0] = v.x; rb[4 * j + 1] = v.y;
                    rb[4 * j + 2] = v.z; rb[4 * j + 3] = v.w;
                }
            } else {
#pragma unroll
                for (int j = 0; j < TN; j++) rb[j] = Bs[k][tcol * TN + j];
            }
#pragma unroll
            for (int i = 0; i < TM; i++)
#pragma unroll
                for (int j = 0; j < TN; j++)
                    acc[i][j] += ra[i] * rb[j];
        }
        __syncthreads();
    }

#pragma unroll
    for (int i = 0; i < TM; i++) {
        int m = brow + trow * TM + i;
#pragma unroll
        for (int j = 0; j < TN; j++) {
            int n = bcol + tcol * TN + j;
            float v = acc[i][j];
            if constexpr (MODE == 1) {
                v += bias[n];
                v = (v > 20.f) ? v : log1pf(expf(v));   // softplus
            }
            C[(long)m * ldc + n] = v;
        }
    }
}

// ---------------- depthwise causal conv (width 4) + SiLU ----------------
__global__ void conv_silu_kernel(const float* __restrict__ conv_w,
                                 const float* __restrict__ conv_b)
{
    long idx = (long)blockIdx.x * blockDim.x + threadIdx.x;
    if (idx >= (long)NTOK * DINNER) return;
    int d = idx % DINNER;
    long t = idx / DINNER;            // token = b*LSEQ + l
    int l = t % LSEQ;

    float acc = conv_b[d];
#pragma unroll
    for (int j = 0; j < DCONV; j++) {
        int ll = l - (DCONV - 1) + j;
        if (ll >= 0)
            acc += conv_w[d * DCONV + j] * g_xz[(t + (ll - l)) * (2 * DINNER) + d];
    }
    // silu
    float s = acc / (1.f + __expf(-acc));
    g_uact[idx] = s;
}

// ---------------- selective scan (one thread per (b,d) channel) ----------------
__global__ void scan_kernel(const float* __restrict__ A_log,
                            const float* __restrict__ Dp)
{
    int tid = blockIdx.x * blockDim.x + threadIdx.x;
    if (tid >= BSZ * DINNER) return;
    int b = tid / DINNER;
    int d = tid % DINNER;

    float an[DSTATE];
#pragma unroll
    for (int n = 0; n < DSTATE; n++) an[n] = -expf(A_log[d * DSTATE + n]);

    float h[DSTATE];
#pragma unroll
    for (int n = 0; n < DSTATE; n++) h[n] = 0.f;

    const float Dd = Dp[d];

    for (int l = 0; l < LSEQ; l++) {
        long t = (long)b * LSEQ + l;
        float dlt = g_delta[t * DINNER + d];
        float uu  = g_uact [t * DINNER + d];
        float zz  = g_xz   [t * (2 * DINNER) + DINNER + d];
        const float* bc = g_xdbl + t * XPROJ;
        float du = dlt * uu;
        float y = 0.f;
#pragma unroll
        for (int n = 0; n < DSTATE; n++) {
            float Bn = bc[DTRANK + n];
            float Cn = bc[DTRANK + DSTATE + n];
            float dA = __expf(dlt * an[n]);
            h[n] = h[n] * dA + du * Bn;
            y += h[n] * Cn;
        }
        y += uu * Dd;
        y *= zz / (1.f + __expf(-zz));        // * silu(z)
        g_y[t * DINNER + d] = y;
    }
}

// ---------------- launch ----------------
extern "C" void kernel_launch(void* const* d_in, const int* in_sizes, int n_in,
                              void* d_out, int out_size)
{
    const float* x         = (const float*)d_in[0];
    const float* in_proj_w = (const float*)d_in[1];
    const float* conv_w    = (const float*)d_in[2];
    const float* conv_b    = (const float*)d_in[3];
    const float* x_proj_w  = (const float*)d_in[4];
    const float* dt_proj_w = (const float*)d_in[5];
    const float* dt_proj_b = (const float*)d_in[6];
    const float* A_log     = (const float*)d_in[7];
    const float* Dp        = (const float*)d_in[8];
    const float* out_proj_w= (const float*)d_in[9];
    float* out = (float*)d_out;

    float *p_xz, *p_uact, *p_xdbl, *p_delta, *p_y;
    cudaGetSymbolAddress((void**)&p_xz,    g_xz);
    cudaGetSymbolAddress((void**)&p_uact,  g_uact);
    cudaGetSymbolAddress((void**)&p_xdbl,  g_xdbl);
    cudaGetSymbolAddress((void**)&p_delta, g_delta);
    cudaGetSymbolAddress((void**)&p_y,     g_y);

    // 1) xz = x @ in_proj_w^T   (8192 x 4096, K=1024)
    {
        dim3 grid(2 * DINNER / 128, NTOK / 128);
        sgemm_nt<128, 128, 16, 8, 8, 0><<<grid, 256>>>(
            NTOK, 2 * DINNER, DMODEL, x, DMODEL, in_proj_w, DMODEL,
            p_xz, 2 * DINNER, nullptr);
    }

    // 2) depthwise conv + silu -> u_act
    {
        long total = (long)NTOK * DINNER;
        conv_silu_kernel<<<(unsigned)((total + 255) / 256), 256>>>(conv_w, conv_b);
    }

    // 3) x_dbl = u_act @ x_proj_w^T   (8192 x 96, K=2048)
    {
        dim3 grid(XPROJ / 96, NTOK / 64);
        sgemm_nt<64, 96, 16, 4, 6, 0><<<grid, 256>>>(
            NTOK, XPROJ, DINNER, p_uact, DINNER, x_proj_w, DINNER,
            p_xdbl, XPROJ, nullptr);
    }

    // 4) delta = softplus(dt_lo @ dt_proj_w^T + dt_proj_b)  (8192 x 2048, K=64)
    {
        dim3 grid(DINNER / 128, NTOK / 128);
        sgemm_nt<128, 128, 16, 8, 8, 1><<<grid, 256>>>(
            NTOK, DINNER, DTRANK, p_xdbl, XPROJ, dt_proj_w, DTRANK,
            p_delta, DINNER, dt_proj_b);
    }

    // 5) selective scan + (y + u*Dp) * silu(z) -> g_y
    {
        scan_kernel<<<(BSZ * DINNER + 255) / 256, 256>>>(A_log, Dp);
    }

    // 6) out = y @ out_proj_w^T   (8192 x 1024, K=2048)
    {
        dim3 grid(DMODEL / 128, NTOK / 128);
        sgemm_nt<128, 128, 16, 8, 8, 0><<<grid, 256>>>(
            NTOK, DMODEL, DINNER, p_y, DINNER, out_proj_w, DINNER,
            out, DMODEL, nullptr);
    }
}

// round 2
// speedup vs baseline: 7.7829x; 7.7829x over previous
#include <cuda_runtime.h>
#include <math.h>
#include <stdint.h>

// ---------------- problem constants ----------------
#define BSZ    2
#define LSEQ   4096
#define DMODEL 1024
#define DINNER 2048
#define DSTATE 16
#define DCONV  4
#define DTRANK 64
#define NTOK   (BSZ * LSEQ)                 // 8192
#define XPROJ  (DTRANK + 2 * DSTATE)        // 96
#define NCHUNK 64
#define CLEN   (LSEQ / NCHUNK)              // 64

// ---------------- scratch (static device globals; no allocs) ----------------
__device__ float g_xz   [NTOK * 2 * DINNER];   // [8192, 4096]  u | z
__device__ float g_uact [NTOK * DINNER];       // [8192, 2048]
__device__ float g_xdbl [NTOK * XPROJ];        // [8192, 96]
__device__ float g_delta[NTOK * DINNER];       // [8192, 2048]
__device__ float g_y    [NTOK * DINNER];       // [8192, 2048]
// scan chunk state: layout [chunk][b][n][d]
__device__ float g_hend [NCHUNK * BSZ * DSTATE * DINNER];
__device__ float g_P    [NCHUNK * BSZ * DSTATE * DINNER];
__device__ float g_hinit[NCHUNK * BSZ * DSTATE * DINNER];

// ---------------- tf32 tensor-core NT GEMM: C[M,N] = A[M,K] * B[N,K]^T --------
// BM=128, BN=128, BK=32, 256 threads (8 warps: 4 in M x 2 in N).
// Warp tile 32x64 = 2 x 8 mma.m16n8k8 tiles.
// MODE 0: plain store.  MODE 1: C = softplus(acc + bias[n]).
// N may be non-multiple of 128 (guarded); M, K must be multiples of 128/32.
#define GBM 128
#define GBN 128
#define GBK 32
#define GPAD 4
#define GSTRIDE (GBK + GPAD)   // 36 floats

__device__ __forceinline__ uint32_t f2tf32(float f) {
    uint32_t u;
    asm("cvt.rna.tf32.f32 %0, %1;" : "=r"(u) : "f"(f));
    return u;
}

template <int MODE>
__global__ __launch_bounds__(256)
void gemm_tf32_nt(int M, int N, int K,
                  const float* __restrict__ A, int lda,
                  const float* __restrict__ B, int ldb,
                  float* __restrict__ C, int ldc,
                  const float* __restrict__ bias)
{
    __shared__ float As[GBM * GSTRIDE];
    __shared__ float Bs[GBN * GSTRIDE];

    const int tid  = threadIdx.x;
    const int lane = tid & 31;
    const int wid  = tid >> 5;
    const int warp_m = wid & 3;        // 0..3
    const int warp_n = wid >> 2;       // 0..1
    const int m_w = warp_m * 32;
    const int n_w = warp_n * 64;
    const int brow = blockIdx.y * GBM;
    const int bcol = blockIdx.x * GBN;
    const int grp = lane >> 2;         // 0..7
    const int tig = lane & 3;          // 0..3

    float acc[2][8][4];
#pragma unroll
    for (int mt = 0; mt < 2; mt++)
#pragma unroll
        for (int nt = 0; nt < 8; nt++)
#pragma unroll
            for (int r = 0; r < 4; r++) acc[mt][nt][r] = 0.f;

    for (int k0 = 0; k0 < K; k0 += GBK) {
        // load A tile: 128 rows x 32 cols = 1024 float4, 4 per thread
#pragma unroll
        for (int i = 0; i < 4; i++) {
            int linear = tid + i * 256;
            int row = linear >> 3;
            int c4  = linear & 7;
            const float4 v = *reinterpret_cast<const float4*>(
                A + (long)(brow + row) * lda + k0 + c4 * 4);
            float4 w;
            w.x = __uint_as_float(f2tf32(v.x));
            w.y = __uint_as_float(f2tf32(v.y));
            w.z = __uint_as_float(f2tf32(v.z));
            w.w = __uint_as_float(f2tf32(v.w));
            *reinterpret_cast<float4*>(&As[row * GSTRIDE + c4 * 4]) = w;
        }
        // load B tile (row n of [N,K]), guard n < N
#pragma unroll
        for (int i = 0; i < 4; i++) {
            int linear = tid + i * 256;
            int row = linear >> 3;
            int c4  = linear & 7;
            float4 w = make_float4(0.f, 0.f, 0.f, 0.f);
            if (bcol + row < N) {
                const float4 v = *reinterpret_cast<const float4*>(
                    B + (long)(bcol + row) * ldb + k0 + c4 * 4);
                w.x = __uint_as_float(f2tf32(v.x));
                w.y = __uint_as_float(f2tf32(v.y));
                w.z = __uint_as_float(f2tf32(v.z));
                w.w = __uint_as_float(f2tf32(v.w));
            }
            *reinterpret_cast<float4*>(&Bs[row * GSTRIDE + c4 * 4]) = w;
        }
        __syncthreads();

#pragma unroll
        for (int kk = 0; kk < GBK; kk += 8) {
            // A fragments: 2 m-tiles x 4 regs
            uint32_t af[2][4];
#pragma unroll
            for (int mt = 0; mt < 2; mt++) {
                int r0 = m_w + mt * 16 + grp;
                af[mt][0] = __float_as_uint(As[r0 * GSTRIDE + kk + tig]);
                af[mt][1] = __float_as_uint(As[(r0 + 8) * GSTRIDE + kk + tig]);
                af[mt][2] = __float_as_uint(As[r0 * GSTRIDE + kk + 4 + tig]);
                af[mt][3] = __float_as_uint(As[(r0 + 8) * GSTRIDE + kk + 4 + tig]);
            }
            // B fragments: 8 n-tiles x 2 regs
            uint32_t bf[8][2];
#pragma unroll
            for (int nt = 0; nt < 8; nt++) {
                int n0 = n_w + nt * 8 + grp;
                bf[nt][0] = __float_as_uint(Bs[n0 * GSTRIDE + kk + tig]);
                bf[nt][1] = __float_as_uint(Bs[n0 * GSTRIDE + kk + 4 + tig]);
            }
#pragma unroll
            for (int mt = 0; mt < 2; mt++)
#pragma unroll
                for (int nt = 0; nt < 8; nt++) {
                    asm volatile(
                        "mma.sync.aligned.m16n8k8.row.col.f32.tf32.tf32.f32 "
                        "{%0,%1,%2,%3}, {%4,%5,%6,%7}, {%8,%9}, {%0,%1,%2,%3};"
                        : "+f"(acc[mt][nt][0]), "+f"(acc[mt][nt][1]),
                          "+f"(acc[mt][nt][2]), "+f"(acc[mt][nt][3])
                        : "r"(af[mt][0]), "r"(af[mt][1]), "r"(af[mt][2]), "r"(af[mt][3]),
                          "r"(bf[nt][0]), "r"(bf[nt][1]));
                }
        }
        __syncthreads();
    }

    // epilogue
#pragma unroll
    for (int mt = 0; mt < 2; mt++) {
        int row0 = brow + m_w + mt * 16 + grp;
#pragma unroll
        for (int nt = 0; nt < 8; nt++) {
            int col = bcol + n_w + nt * 8 + tig * 2;
            if (col < N) {
                float v0 = acc[mt][nt][0], v1 = acc[mt][nt][1];
                float v2 = acc[mt][nt][2], v3 = acc[mt][nt][3];
                if constexpr (MODE == 1) {
                    float b0 = bias[col], b1 = bias[col + 1];
                    v0 += b0; v1 += b1; v2 += b0; v3 += b1;
                    v0 = (v0 > 20.f) ? v0 : log1pf(expf(v0));
                    v1 = (v1 > 20.f) ? v1 : log1pf(expf(v1));
                    v2 = (v2 > 20.f) ? v2 : log1pf(expf(v2));
                    v3 = (v3 > 20.f) ? v3 : log1pf(expf(v3));
                }
                *reinterpret_cast<float2*>(C + (long)row0 * ldc + col) =
                    make_float2(v0, v1);
                *reinterpret_cast<float2*>(C + (long)(row0 + 8) * ldc + col) =
                    make_float2(v2, v3);
            }
        }
    }
}

// ---------------- depthwise causal conv (width 4) + SiLU ----------------
__global__ void conv_silu_kernel(const float* __restrict__ conv_w,
                                 const float* __restrict__ conv_b)
{
    long idx = (long)blockIdx.x * blockDim.x + threadIdx.x;
    if (idx >= (long)NTOK * DINNER) return;
    int d = idx % DINNER;
    long t = idx / DINNER;
    int l = t % LSEQ;

    float acc = conv_b[d];
#pragma unroll
    for (int j = 0; j < DCONV; j++) {
        int ll = l - (DCONV - 1) + j;
        if (ll >= 0)
            acc += conv_w[d * DCONV + j] * g_xz[(t + (ll - l)) * (2 * DINNER) + d];
    }
    float s = acc / (1.f + __expf(-acc));
    g_uact[idx] = s;
}

// ---------------- chunked parallel scan ----------------
// Phase A: each thread runs one chunk for one (b,d) from h=0; stores h_end and
//          decay product P = prod(dA) per state.
__global__ void scanA_kernel(const float* __restrict__ A_log)
{
    int idx = blockIdx.x * blockDim.x + threadIdx.x;
    if (idx >= NCHUNK * BSZ * DINNER) return;
    int d = idx % DINNER;
    int rem = idx / DINNER;
    int b = rem % BSZ;
    int c = rem / BSZ;

    float an[DSTATE];
#pragma unroll
    for (int n = 0; n < DSTATE; n++) an[n] = -expf(A_log[d * DSTATE + n]);

    float h[DSTATE], P[DSTATE];
#pragma unroll
    for (int n = 0; n < DSTATE; n++) { h[n] = 0.f; P[n] = 1.f; }

    for (int s = 0; s < CLEN; s++) {
        long t = (long)b * LSEQ + c * CLEN + s;
        float dlt = g_delta[t * DINNER + d];
        float uu  = g_uact [t * DINNER + d];
        const float* bc = g_xdbl + t * XPROJ;
        float du = dlt * uu;
#pragma unroll
        for (int n = 0; n < DSTATE; n++) {
            float dA = __expf(dlt * an[n]);
            h[n] = h[n] * dA + du * bc[DTRANK + n];
            P[n] *= dA;
        }
    }
    long base = (((long)c * BSZ + b) * DSTATE) * DINNER + d;
#pragma unroll
    for (int n = 0; n < DSTATE; n++) {
        g_hend[base + (long)n * DINNER] = h[n];
        g_P   [base + (long)n * DINNER] = P[n];
    }
}

// Phase B: sequentially combine chunk states per (b,d). h_init[c+1] = P_c*h_init[c] + hend_c.
__global__ void scanB_kernel()
{
    int idx = blockIdx.x * blockDim.x + threadIdx.x;
    if (idx >= BSZ * DINNER) return;
    int d = idx % DINNER;
    int b = idx / DINNER;

    float h[DSTATE];
#pragma unroll
    for (int n = 0; n < DSTATE; n++) h[n] = 0.f;

    for (int c = 0; c < NCHUNK; c++) {
        long base = (((long)c * BSZ + b) * DSTATE) * DINNER + d;
#pragma unroll
        for (int n = 0; n < DSTATE; n++) {
            g_hinit[base + (long)n * DINNER] = h[n];
            h[n] = g_P[base + (long)n * DINNER] * h[n] +
                   g_hend[base + (long)n * DINNER];
        }
    }
}

// Phase C: rerun each chunk from its true initial state, produce y with epilogue.
__global__ void scanC_kernel(const float* __restrict__ A_log,
                             const float* __restrict__ Dp)
{
    int idx = blockIdx.x * blockDim.x + threadIdx.x;
    if (idx >= NCHUNK * BSZ * DINNER) return;
    int d = idx % DINNER;
    int rem = idx / DINNER;
    int b = rem % BSZ;
    int c = rem / BSZ;

    float an[DSTATE];
#pragma unroll
    for (int n = 0; n < DSTATE; n++) an[n] = -expf(A_log[d * DSTATE + n]);

    float h[DSTATE];
    long base = (((long)c * BSZ + b) * DSTATE) * DINNER + d;
#pragma unroll
    for (int n = 0; n < DSTATE; n++) h[n] = g_hinit[base + (long)n * DINNER];

    const float Dd = Dp[d];

    for (int s = 0; s < CLEN; s++) {
        long t = (long)b * LSEQ + c * CLEN + s;
        float dlt = g_delta[t * DINNER + d];
        float uu  = g_uact [t * DINNER + d];
        float zz  = g_xz   [t * (2 * DINNER) + DINNER + d];
        const float* bc = g_xdbl + t * XPROJ;
        float du = dlt * uu;
        float y = 0.f;
#pragma unroll
        for (int n = 0; n < DSTATE; n++) {
            float dA = __expf(dlt * an[n]);
            h[n] = h[n] * dA + du * bc[DTRANK + n];
            y += h[n] * bc[DTRANK + DSTATE + n];
        }
        y += uu * Dd;
        y *= zz / (1.f + __expf(-zz));
        g_y[t * DINNER + d] = y;
    }
}

// ---------------- launch ----------------
extern "C" void kernel_launch(void* const* d_in, const int* in_sizes, int n_in,
                              void* d_out, int out_size)
{
    const float* x         = (const float*)d_in[0];
    const float* in_proj_w = (const float*)d_in[1];
    const float* conv_w    = (const float*)d_in[2];
    const float* conv_b    = (const float*)d_in[3];
    const float* x_proj_w  = (const float*)d_in[4];
    const float* dt_proj_w = (const float*)d_in[5];
    const float* dt_proj_b = (const float*)d_in[6];
    const float* A_log     = (const float*)d_in[7];
    const float* Dp        = (const float*)d_in[8];
    const float* out_proj_w= (const float*)d_in[9];
    float* out = (float*)d_out;

    float *p_xz, *p_uact, *p_xdbl, *p_delta, *p_y;
    cudaGetSymbolAddress((void**)&p_xz,    g_xz);
    cudaGetSymbolAddress((void**)&p_uact,  g_uact);
    cudaGetSymbolAddress((void**)&p_xdbl,  g_xdbl);
    cudaGetSymbolAddress((void**)&p_delta, g_delta);
    cudaGetSymbolAddress((void**)&p_y,     g_y);

    // 1) xz = x @ in_proj_w^T   (8192 x 4096, K=1024)
    {
        dim3 grid((2 * DINNER + GBN - 1) / GBN, NTOK / GBM);
        gemm_tf32_nt<0><<<grid, 256>>>(
            NTOK, 2 * DINNER, DMODEL, x, DMODEL, in_proj_w, DMODEL,
            p_xz, 2 * DINNER, nullptr);
    }

    // 2) depthwise conv + silu -> u_act
    {
        long total = (long)NTOK * DINNER;
        conv_silu_kernel<<<(unsigned)((total + 255) / 256), 256>>>(conv_w, conv_b);
    }

    // 3) x_dbl = u_act @ x_proj_w^T   (8192 x 96, K=2048)
    {
        dim3 grid((XPROJ + GBN - 1) / GBN, NTOK / GBM);
        gemm_tf32_nt<0><<<grid, 256>>>(
            NTOK, XPROJ, DINNER, p_uact, DINNER, x_proj_w, DINNER,
            p_xdbl, XPROJ, nullptr);
    }

    // 4) delta = softplus(dt_lo @ dt_proj_w^T + dt_proj_b)  (8192 x 2048, K=64)
    {
        dim3 grid((DINNER + GBN - 1) / GBN, NTOK / GBM);
        gemm_tf32_nt<1><<<grid, 256>>>(
            NTOK, DINNER, DTRANK, p_xdbl, XPROJ, dt_proj_w, DTRANK,
            p_delta, DINNER, dt_proj_b);
    }

    // 5) chunked selective scan
    {
        int totalA = NCHUNK * BSZ * DINNER;
        scanA_kernel<<<(totalA + 255) / 256, 256>>>(A_log);
        scanB_kernel<<<(BSZ * DINNER + 255) / 256, 256>>>();
        scanC_kernel<<<(totalA + 255) / 256, 256>>>(A_log, Dp);
    }

    // 6) out = y @ out_proj_w^T   (8192 x 1024, K=2048)
    {
        dim3 grid((DMODEL + GBN - 1) / GBN, NTOK / GBM);
        gemm_tf32_nt<0><<<grid, 256>>>(
            NTOK, DMODEL, DINNER, p_y, DINNER, out_proj_w, DINNER,
            out, DMODEL, nullptr);
    }
}